// round 8
// baseline (speedup 1.0000x reference)
#include <cuda_runtime.h>
#include <cuda_fp16.h>
#include <cstdint>
#include <math.h>

// ---------------- problem constants ----------------
#define BS 8192
#define LH 20
#define NF 172
#define TF 172
#define DD 860            // D
#define DH 430            // D / H
#define NROWS (BS*LH)     // 163840
#define QKVN 2580         // 3*D
#define KP1 896           // DD padded (downstream gemms)
#define KP2 192           // NF padded
#define KF  704           // reduced qkv K: histS|histD|edge|time

// fp16 weight scratch offsets (in halfs)
#define W_INPROJ 0                                  // [2580][704]
#define W_OUTPROJ (W_INPROJ + (size_t)QKVN*KF)
#define W_OUTFN   (W_OUTPROJ + (size_t)DD*KP1)
#define W_FC1     (W_OUTFN + (size_t)NF*KP1)
#define W_FC2     (W_FC1 + (size_t)NF*KP1)
#define W_ANON    (W_FC2 + (size_t)NF*KP2)          // [2580][192]
#define W_TOTAL   (W_ANON + (size_t)QKVN*KP2)

#define YLD 5160          // Y row stride (2*QKVN)

// ---------------- scratch ----------------
__device__ __half g_F[(size_t)NROWS * KF];
__device__ __half g_QKV[(size_t)NROWS * QKVN];
__device__ __half g_CTXM[(size_t)BS * KP1];
__device__ __half g_OM[(size_t)BS * KP1];
__device__ __half g_X[(size_t)BS * KP1];
__device__ __half g_H1[(size_t)BS * KP2];
__device__ __half g_WR[W_TOTAL];
__device__ __half g_WSD[(size_t)YLD * KP2];         // [Ws;Wd] [5160][192]
__device__ __half g_Y[(size_t)BS * YLD];            // rn projections
__device__ __half g_TA[(size_t)128 * QKVN];         // anony table (M padded to 128)
__device__ __half g_RN[(size_t)BS * KP2];           // node_emb[nids] fp16
__device__ __half g_AE[(size_t)128 * KP2];          // anony_emb fp16 (21 real rows)
__device__ int2   g_META[(size_t)NROWS];            // {yoff(-1=skip), aoff}

// ---------------- helpers ----------------
__device__ __forceinline__ uint32_t smem_u32(const void* p) {
    uint32_t a;
    asm("{ .reg .u64 t; cvta.to.shared.u64 t, %1; cvt.u32.u64 %0, t; }" : "=r"(a) : "l"(p));
    return a;
}
__device__ __forceinline__ void cp16(uint32_t dst, const void* src, int bytes) {
    asm volatile("cp.async.cg.shared.global [%0], [%1], 16, %2;"
                 :: "r"(dst), "l"(src), "r"(bytes));
}
__device__ __forceinline__ void cp_commit() {
    asm volatile("cp.async.commit_group;" ::: "memory");
}
template <int N>
__device__ __forceinline__ void cp_wait() {
    asm volatile("cp.async.wait_group %0;" :: "n"(N) : "memory");
}
__device__ __forceinline__ void mma_f16(float* c, const uint32_t* a, uint32_t b0, uint32_t b1) {
    asm volatile(
        "mma.sync.aligned.m16n8k16.row.col.f32.f16.f16.f32 "
        "{%0,%1,%2,%3}, {%4,%5,%6,%7}, {%8,%9}, {%0,%1,%2,%3};\n"
        : "+f"(c[0]), "+f"(c[1]), "+f"(c[2]), "+f"(c[3])
        : "r"(a[0]), "r"(a[1]), "r"(a[2]), "r"(a[3]), "r"(b0), "r"(b1));
}
__device__ __forceinline__ void ldsm_x4(uint32_t& r0, uint32_t& r1, uint32_t& r2, uint32_t& r3,
                                        uint32_t addr) {
    asm volatile("ldmatrix.sync.aligned.m8n8.x4.shared.b16 {%0,%1,%2,%3}, [%4];"
                 : "=r"(r0), "=r"(r1), "=r"(r2), "=r"(r3) : "r"(addr));
}

// ---------------- conversion kernels ----------------
// generic: dst[r][c] = fp16(src[r*srcld + srcoff + c]) for c<K, dst row stride KPad
__global__ void cvt_w(const float* __restrict__ src, __half* __restrict__ dst,
                      int rows, int K, int KPad, int srcld, int srcoff)
{
    int i = blockIdx.x * 256 + threadIdx.x;
    if (i < rows * K) {
        int r = i / K, c = i % K;
        dst[(size_t)r * KPad + c] = __float2half_rn(src[(size_t)r * srcld + srcoff + c]);
    }
}
// in_proj main-B: [2580][704] <- cols {0:344, 516:860}
__global__ void cvt_inproj(const float* __restrict__ src, __half* __restrict__ dst)
{
    int i = blockIdx.x * 256 + threadIdx.x;
    if (i < QKVN * 688) {
        int r = i / 688, c = i % 688;
        int sc = (c < 344) ? c : c + 172;
        dst[(size_t)r * KF + c] = __float2half_rn(src[(size_t)r * DD + sc]);
    }
}
// RN[b][c] = node_emb[nids[b]][c]
__global__ void prep_rn(const int* __restrict__ nids, const float* __restrict__ node_emb)
{
    int i = blockIdx.x * 256 + threadIdx.x;
    if (i < BS * NF) {
        int b = i / NF, c = i % NF;
        g_RN[(size_t)b * KP2 + c] = __float2half_rn(node_emb[(size_t)nids[b] * NF + c]);
    }
}
__global__ void prep_ae(const float* __restrict__ anony_emb)
{
    int i = blockIdx.x * 256 + threadIdx.x;
    if (i < 21 * NF) {
        int r = i / NF, c = i % NF;
        g_AE[(size_t)r * KP2 + c] = __float2half_rn(anony_emb[(size_t)r * NF + c]);
    }
}

// ---------------- fp16 GEMM, 4-stage cp.async, ldmatrix ----------------
#define GBM 128
#define GBN 256
#define A_BYTES (GBM * 144)
#define B_BYTES (GBN * 144)
#define STAGE_BYTES (A_BYTES + B_BYTES)
#define NSTAGE 4
#define GSMEM (NSTAGE * STAGE_BYTES)

__device__ __forceinline__ void issue_tile(const __half* __restrict__ A,
                                           const __half* __restrict__ B,
                                           uint32_t sstage, int m0, int n0, int k0,
                                           int N, int K, int t)
{
    #pragma unroll
    for (int i = 0; i < 4; i++) {
        int id = t + (i << 8);
        int row = id >> 3;
        int c8 = (id & 7) << 3;
        const __half* src = A + (size_t)(m0 + row) * K + k0 + c8;
        cp16(sstage + row * 144 + (id & 7) * 16, src, 16);
    }
    #pragma unroll
    for (int i = 0; i < 8; i++) {
        int id = t + (i << 8);
        int row = id >> 3;
        int c8 = (id & 7) << 3;
        int bytes = (n0 + row < N) ? 16 : 0;
        const __half* src = bytes ? (B + (size_t)(n0 + row) * K + k0 + c8) : B;
        cp16(sstage + A_BYTES + row * 144 + (id & 7) * 16, src, bytes);
    }
}

__global__ void __launch_bounds__(256, 1)
gemm_f16(const __half* __restrict__ A, const __half* __restrict__ B,
         const float* __restrict__ bias,
         __half* __restrict__ C, int ldc,
         float* __restrict__ Cf, int ldcf,
         float* __restrict__ aux,
         int M, int N, int K, int relu_a,
         const __half* __restrict__ Yt, const __half* __restrict__ Ta,
         const int2* __restrict__ meta)
{
    extern __shared__ __align__(16) char sm[];
    uint32_t sbase = smem_u32(sm);

    int t = threadIdx.x;
    int warp = t >> 5, lane = t & 31;
    int m0 = blockIdx.y * GBM;
    int n0 = blockIdx.x * GBN;
    int mbase = (warp & 1) * 64;
    int nbase = (warp >> 1) * 64;

    uint32_t a_lane = (uint32_t)(lane & 15) * 144 + ((lane >> 4) << 4);
    uint32_t b_lane = (uint32_t)((lane & 7) | ((lane >> 1) & 8)) * 144 + (((lane >> 3) & 1) << 4);

    float acc[4][8][4];
    #pragma unroll
    for (int mi = 0; mi < 4; mi++)
        #pragma unroll
        for (int ni = 0; ni < 8; ni++)
            #pragma unroll
            for (int r = 0; r < 4; r++) acc[mi][ni][r] = 0.0f;

    int KT = K >> 6;

    issue_tile(A, B, sbase, m0, n0, 0, N, K, t);
    cp_commit();
    if (KT > 1) issue_tile(A, B, sbase + STAGE_BYTES, m0, n0, 64, N, K, t);
    cp_commit();
    if (KT > 2) issue_tile(A, B, sbase + 2 * STAGE_BYTES, m0, n0, 128, N, K, t);
    cp_commit();

    const __half2 hz = __float2half2_rn(0.0f);

    int scur = 0, snxt = 3;
    for (int kt = 0; kt < KT; kt++) {
        if (kt + 3 < KT)
            issue_tile(A, B, sbase + snxt * STAGE_BYTES, m0, n0, (kt + 3) << 6, N, K, t);
        cp_commit();
        cp_wait<3>();
        __syncthreads();

        uint32_t sA = sbase + scur * STAGE_BYTES;
        uint32_t sB = sA + A_BYTES;

        #pragma unroll
        for (int kk = 0; kk < 4; kk++) {
            uint32_t kof = (uint32_t)kk * 32;
            uint32_t a[4][4];
            #pragma unroll
            for (int mi = 0; mi < 4; mi++)
                ldsm_x4(a[mi][0], a[mi][1], a[mi][2], a[mi][3],
                        sA + (uint32_t)(mbase + mi * 16) * 144 + kof + a_lane);
            if (relu_a) {
                #pragma unroll
                for (int mi = 0; mi < 4; mi++)
                    #pragma unroll
                    for (int q = 0; q < 4; q++) {
                        __half2 h = *reinterpret_cast<__half2*>(&a[mi][q]);
                        h = __hmax2(h, hz);
                        a[mi][q] = *reinterpret_cast<uint32_t*>(&h);
                    }
            }
            uint32_t b[8][2];
            #pragma unroll
            for (int np = 0; np < 4; np++)
                ldsm_x4(b[2*np][0], b[2*np][1], b[2*np+1][0], b[2*np+1][1],
                        sB + (uint32_t)(nbase + np * 16) * 144 + kof + b_lane);
            #pragma unroll
            for (int mi = 0; mi < 4; mi++)
                #pragma unroll
                for (int ni = 0; ni < 8; ni++)
                    mma_f16(acc[mi][ni], a[mi], b[ni][0], b[ni][1]);
        }

        scur = (scur == NSTAGE - 1) ? 0 : scur + 1;
        snxt = (snxt == NSTAGE - 1) ? 0 : snxt + 1;
    }

    // epilogue
    #pragma unroll
    for (int mi = 0; mi < 4; mi++) {
        int r0 = m0 + mbase + mi * 16 + (lane >> 2);
        int r1 = r0 + 8;
        int2 mt0 = meta ? meta[r0] : make_int2(-1, 0);
        int2 mt1 = meta ? meta[r1] : make_int2(-1, 0);
        #pragma unroll
        for (int ni = 0; ni < 8; ni++) {
            int col = n0 + nbase + ni * 8 + (lane & 3) * 2;
            if (col < N) {
                float b0 = bias ? bias[col] : 0.0f;
                float b1 = bias ? bias[col + 1] : 0.0f;
                float v00 = acc[mi][ni][0] + b0, v01 = acc[mi][ni][1] + b1;
                float v10 = acc[mi][ni][2] + b0, v11 = acc[mi][ni][3] + b1;
                if (meta) {
                    if (mt0.x >= 0) {
                        __half2 y = *(const __half2*)(Yt + (size_t)mt0.x + col);
                        __half2 ta = *(const __half2*)(Ta + (size_t)mt0.y + col);
                        float2 yf = __half22float2(y), tf = __half22float2(ta);
                        v00 += yf.x + tf.x; v01 += yf.y + tf.y;
                    }
                    if (mt1.x >= 0) {
                        __half2 y = *(const __half2*)(Yt + (size_t)mt1.x + col);
                        __half2 ta = *(const __half2*)(Ta + (size_t)mt1.y + col);
                        float2 yf = __half22float2(y), tf = __half22float2(ta);
                        v10 += yf.x + tf.x; v11 += yf.y + tf.y;
                    }
                }
                if (C) {
                    *(__half2*)(C + (size_t)r0 * ldc + col) = __floats2half2_rn(v00, v01);
                    *(__half2*)(C + (size_t)r1 * ldc + col) = __floats2half2_rn(v10, v11);
                }
                if (Cf) {
                    Cf[(size_t)r0 * ldcf + col]     = v00;
                    Cf[(size_t)r0 * ldcf + col + 1] = v01;
                    Cf[(size_t)r1 * ldcf + col]     = v10;
                    Cf[(size_t)r1 * ldcf + col + 1] = v11;
                }
                if (aux) {
                    aux[(size_t)r0 * N + col]     = v00;
                    aux[(size_t)r0 * N + col + 1] = v01;
                    aux[(size_t)r1 * N + col]     = v10;
                    aux[(size_t)r1 * N + col + 1] = v11;
                }
            }
        }
    }
}

// ---------------- build kernel: reduced F + meta + last_event_feat ----------------
__global__ void build_kernel(const int* __restrict__ nids,
                             const int* __restrict__ hist_nids,
                             const int* __restrict__ aids,
                             const int* __restrict__ eids,
                             const float* __restrict__ ts,
                             const int* __restrict__ dirs,
                             const float* __restrict__ node_emb,
                             const float* __restrict__ edge_emb,
                             const float* __restrict__ anony_emb,
                             const float* __restrict__ time_w,
                             const float* __restrict__ time_b,
                             float* __restrict__ out_pts)
{
    int row = blockIdx.x;
    int b = row / LH, l = row % LH;
    int hn  = hist_nids[row];
    int d   = dirs[row];
    int aid = aids[row];
    int eid = eids[row];
    float tlast = ts[b*LH + (LH-1)];
    float dt = tlast - ts[row];
    bool last = (l == LH-1);
    __half* Frow = g_F + (size_t)row * KF;
    int tid = threadIdx.x;
    const __half hzero = __float2half_rn(0.0f);

    // F layout: [0:172) hist via Ws (d==0), [172:344) hist via Wd (d==1),
    //           [344:516) edge, [516:688) time, [688:704) pad(zero)
    for (int c = tid; c < 688; c += blockDim.x) {
        float v; bool zero = false;
        if (c < 172) {
            if (last || d == 1) zero = true;
            v = zero ? 0.f : node_emb[(size_t)hn*NF + c];
        } else if (c < 344) {
            if (last || d == 0) zero = true;
            v = zero ? 0.f : node_emb[(size_t)hn*NF + (c-172)];
        } else if (c < 516) {
            v = last ? 0.f : edge_emb[(size_t)eid*NF + (c-344)];
        } else {
            int f = c - 516;
            v = cosf(dt * time_w[f] + time_b[f]);
        }
        Frow[c] = __float2half_rn(v);
    }

    if (last) {
        int rn = nids[b];
        int src = d ? rn : hn;
        int dst = d ? hn : rn;
        for (int c = tid; c < 688; c += blockDim.x) {
            float v;
            if      (c < 172) v = node_emb[(size_t)src*NF + c];
            else if (c < 344) v = node_emb[(size_t)dst*NF + (c-172)];
            else if (c < 516) v = anony_emb[(size_t)aid*NF + (c-344)];
            else              v = edge_emb[(size_t)eid*NF + (c-516)];
            g_X[(size_t)b*KP1 + NF + c] = __float2half_rn(v);
        }
        if (tid == 0) out_pts[b] = tlast;
    }
    if (tid == 0) {
        // yoff: row's rn goes through Ws when d==1 (src slot), Wd when d==0
        g_META[row] = last ? make_int2(-1, 0)
                           : make_int2(b * YLD + (d ? 0 : QKVN), aid * QKVN);
    }
}

// ---------------- attention + q-mean fused kernel ----------------
#define ATTN_SMEM (2 * LH * 432 * 4)

__global__ void __launch_bounds__(256)
attn_kernel(const int* __restrict__ hist_nids)
{
    extern __shared__ __align__(16) float qk[];
    float* Qs = qk;
    float* Ks = qk + LH * 432;
    __shared__ float sc[LH][LH];
    __shared__ float abar[LH];
    __shared__ int   msk[LH];

    int b = blockIdx.x;
    int t = threadIdx.x;
    int warp = t >> 5, lane = t & 31;
    const __half* qkvb = g_QKV + (size_t)b * LH * QKVN;
    const float scale = 0.048224282f;

    if (t < LH) msk[t] = (hist_nids[b*LH + t] == 0 && t != LH-1) ? 1 : 0;

    for (int h = 0; h < 2; h++) {
        int off = h * DH;
        __syncthreads();
        for (int i = t; i < LH * 432; i += 256) {
            int j = i / 432, c = i % 432;
            Qs[i] = (c < DH) ? __half2float(qkvb[(size_t)j*QKVN + off + c]) : 0.0f;
            Ks[i] = (c < DH) ? __half2float(qkvb[(size_t)j*QKVN + DD + off + c]) : 0.0f;
        }
        __syncthreads();

        int nr = (warp < 4) ? 3 : 2;
        float acc[3][LH];
        #pragma unroll
        for (int ri = 0; ri < 3; ri++)
            #pragma unroll
            for (int j = 0; j < LH; j++) acc[ri][j] = 0.0f;

        #pragma unroll
        for (int it = 0; it < 4; it++) {
            int dd = it * 128 + lane * 4;
            if (dd < 432) {
                float4 q0 = *(const float4*)(Qs + warp * 432 + dd);
                float4 q1 = *(const float4*)(Qs + (warp + 8) * 432 + dd);
                float4 q2 = (nr == 3) ? *(const float4*)(Qs + (warp + 16) * 432 + dd)
                                      : make_float4(0.f, 0.f, 0.f, 0.f);
                #pragma unroll
                for (int j = 0; j < LH; j++) {
                    float4 k4 = *(const float4*)(Ks + j * 432 + dd);
                    acc[0][j] += q0.x*k4.x + q0.y*k4.y + q0.z*k4.z + q0.w*k4.w;
                    acc[1][j] += q1.x*k4.x + q1.y*k4.y + q1.z*k4.z + q1.w*k4.w;
                    if (nr == 3)
                        acc[2][j] += q2.x*k4.x + q2.y*k4.y + q2.z*k4.z + q2.w*k4.w;
                }
            }
        }
        #pragma unroll
        for (int ri = 0; ri < 3; ri++) {
            if (ri < nr) {
                int row = warp + ri * 8;
                #pragma unroll
                for (int j = 0; j < LH; j++) {
                    float s = acc[ri][j];
                    #pragma unroll
                    for (int o = 16; o > 0; o >>= 1)
                        s += __shfl_xor_sync(0xffffffffu, s, o);
                    if (lane == 0) sc[row][j] = s * scale;
                }
            }
        }
        __syncthreads();

        if (warp == 0 && lane < LH) {
            int i = lane;
            float mx = -1e30f;
            #pragma unroll
            for (int j = 0; j < LH; j++)
                if (!msk[j]) mx = fmaxf(mx, sc[i][j]);
            float e[LH]; float s = 0.f;
            #pragma unroll
            for (int j = 0; j < LH; j++) {
                float ev = msk[j] ? 0.f : __expf(sc[i][j] - mx);
                e[j] = ev; s += ev;
            }
            float inv = 1.f / s;
            #pragma unroll
            for (int j = 0; j < LH; j++) sc[i][j] = e[j] * inv;
        }
        __syncthreads();

        if (warp == 0 && lane < LH) {
            int j = lane; float s = 0.f;
            #pragma unroll
            for (int i = 0; i < LH; i++) s += sc[i][j];
            abar[j] = s * (1.0f / LH);
        }
        __syncthreads();

        for (int dd = t; dd < DH; dd += 256) {
            float s = 0.f;
            #pragma unroll
            for (int j = 0; j < LH; j++)
                s += abar[j] * __half2float(qkvb[(size_t)j*QKVN + 2*DD + off + dd]);
            g_CTXM[(size_t)b*KP1 + off + dd] = __float2half_rn(s);
        }
    }
}

// ---------------- launch ----------------
extern "C" void kernel_launch(void* const* d_in, const int* in_sizes, int n_in,
                              void* d_out, int out_size)
{
    const int*   nids       = (const int*)  d_in[0];
    const int*   hist_nids  = (const int*)  d_in[1];
    const int*   aids       = (const int*)  d_in[2];
    const int*   eids       = (const int*)  d_in[3];
    const float* hist_ts    = (const float*)d_in[4];
    const int*   dirs       = (const int*)  d_in[5];
    const float* node_emb   = (const float*)d_in[6];
    const float* edge_emb   = (const float*)d_in[7];
    const float* anony_emb  = (const float*)d_in[8];
    const float* time_w     = (const float*)d_in[9];
    const float* time_b     = (const float*)d_in[10];
    const float* in_proj_w  = (const float*)d_in[11];
    const float* in_proj_b  = (const float*)d_in[12];
    const float* out_proj_w = (const float*)d_in[13];
    const float* out_proj_b = (const float*)d_in[14];
    const float* outfn_w    = (const float*)d_in[15];
    const float* outfn_b    = (const float*)d_in[16];
    const float* fc1_w      = (const float*)d_in[17];
    const float* fc1_b      = (const float*)d_in[18];
    const float* fc2_w      = (const float*)d_in[19];
    const float* fc2_b      = (const float*)d_in[20];

    float* out = (float*)d_out;
    float* out_hr  = out + (size_t)BS * NF;
    float* out_pts = out + (size_t)2 * BS * NF;

    __half* QKV  = nullptr; cudaGetSymbolAddress((void**)&QKV,  g_QKV);
    __half* F    = nullptr; cudaGetSymbolAddress((void**)&F,    g_F);
    __half* CTXM = nullptr; cudaGetSymbolAddress((void**)&CTXM, g_CTXM);
    __half* OM   = nullptr; cudaGetSymbolAddress((void**)&OM,   g_OM);
    __half* X    = nullptr; cudaGetSymbolAddress((void**)&X,    g_X);
    __half* H1   = nullptr; cudaGetSymbolAddress((void**)&H1,   g_H1);
    __half* WR   = nullptr; cudaGetSymbolAddress((void**)&WR,   g_WR);
    __half* WSD  = nullptr; cudaGetSymbolAddress((void**)&WSD,  g_WSD);
    __half* Y    = nullptr; cudaGetSymbolAddress((void**)&Y,    g_Y);
    __half* TA   = nullptr; cudaGetSymbolAddress((void**)&TA,   g_TA);
    __half* RN   = nullptr; cudaGetSymbolAddress((void**)&RN,   g_RN);
    __half* AE   = nullptr; cudaGetSymbolAddress((void**)&AE,   g_AE);
    int2*   META = nullptr; cudaGetSymbolAddress((void**)&META, g_META);

    cudaFuncSetAttribute(gemm_f16, cudaFuncAttributeMaxDynamicSharedMemorySize, GSMEM);
    cudaFuncSetAttribute(attn_kernel, cudaFuncAttributeMaxDynamicSharedMemorySize, ATTN_SMEM);

    // 0) weight conversions
    cvt_inproj<<<(QKVN*688 + 255)/256, 256>>>(in_proj_w, WR + W_INPROJ);
    cvt_w<<<(DD*DD   + 255)/256, 256>>>(out_proj_w, WR + W_OUTPROJ, DD,   DD, KP1, DD, 0);
    cvt_w<<<(NF*DD   + 255)/256, 256>>>(outfn_w,    WR + W_OUTFN,   NF,   DD, KP1, DD, 0);
    cvt_w<<<(NF*DD   + 255)/256, 256>>>(fc1_w,      WR + W_FC1,     NF,   DD, KP1, DD, 0);
    cvt_w<<<(NF*NF   + 255)/256, 256>>>(fc2_w,      WR + W_FC2,     NF,   NF, KP2, NF, 0);
    cvt_w<<<(QKVN*NF + 255)/256, 256>>>(in_proj_w,  WR + W_ANON,    QKVN, NF, KP2, DD, 344);
    cvt_w<<<(QKVN*NF + 255)/256, 256>>>(in_proj_w,  WSD,              QKVN, NF, KP2, DD, 0);
    cvt_w<<<(QKVN*NF + 255)/256, 256>>>(in_proj_w,  WSD + (size_t)QKVN*KP2, QKVN, NF, KP2, DD, 172);
    prep_rn<<<(BS*NF + 255)/256, 256>>>(nids, node_emb);
    prep_ae<<<(21*NF + 255)/256, 256>>>(anony_emb);

    // 1) build features + meta
    build_kernel<<<NROWS, 128>>>(nids, hist_nids, aids, eids, hist_ts, dirs,
                                 node_emb, edge_emb, anony_emb, time_w, time_b,
                                 out_pts);

    // 2a) Y = RN @ [Ws;Wd]^T   [8192 x 5160]
    gemm_f16<<<dim3((YLD + GBN - 1)/GBN, BS/GBM), 256, GSMEM>>>(
        RN, WSD, nullptr, Y, YLD, nullptr, 0, nullptr,
        BS, YLD, KP2, 0, nullptr, nullptr, nullptr);
    // 2b) T_anon = AE @ W_anon^T   [128 x 2580] (21 real rows)
    gemm_f16<<<dim3((QKVN + GBN - 1)/GBN, 1), 256, GSMEM>>>(
        AE, WR + W_ANON, nullptr, TA, QKVN, nullptr, 0, nullptr,
        128, QKVN, KP2, 0, nullptr, nullptr, nullptr);

    // 3) qkv = F @ W'[hist|edge|time]^T + bias + Y[yoff] + T_anon[aoff]
    gemm_f16<<<dim3((QKVN + GBN - 1)/GBN, NROWS/GBM), 256, GSMEM>>>(
        F, WR + W_INPROJ, in_proj_b, QKV, QKVN, nullptr, 0, nullptr,
        NROWS, QKVN, KF, 0, Y, TA, META);

    // 4) attention (+ mean over queries)
    attn_kernel<<<BS, 256, ATTN_SMEM>>>(hist_nids);

    // 5) om = ctx_mean @ out_proj_w^T + b
    gemm_f16<<<dim3(4, BS/GBM), 256, GSMEM>>>(
        CTXM, WR + W_OUTPROJ, out_proj_b, OM, KP1, nullptr, 0, nullptr,
        BS, DD, KP1, 0, nullptr, nullptr, nullptr);

    // 6) h_prev_left = relu(om) @ outfn_w^T + b
    gemm_f16<<<dim3(1, BS/GBM), 256, GSMEM>>>(
        OM, WR + W_OUTFN, outfn_b, X, KP1, nullptr, 0, out,
        BS, NF, KP1, 1, nullptr, nullptr, nullptr);

    // 7) H1 = X @ fc1_w^T + b
    gemm_f16<<<dim3(1, BS/GBM), 256, GSMEM>>>(
        X, WR + W_FC1, fc1_b, H1, KP2, nullptr, 0, nullptr,
        BS, NF, KP1, 0, nullptr, nullptr, nullptr);

    // 8) h_prev_right = relu(H1) @ fc2_w^T + b
    gemm_f16<<<dim3(1, BS/GBM), 256, GSMEM>>>(
        H1, WR + W_FC2, fc2_b, nullptr, 0, out_hr, NF, nullptr,
        BS, NF, KP2, 1, nullptr, nullptr, nullptr);
}

// round 9
// speedup vs baseline: 1.2078x; 1.2078x over previous
#include <cuda_runtime.h>
#include <cuda_fp16.h>
#include <cstdint>
#include <math.h>

// ---------------- problem constants ----------------
#define BS 8192
#define LH 20
#define NF 172
#define TF 172
#define DD 860            // D
#define DH 430            // D / H
#define NROWS (BS*LH)     // 163840
#define QKVN 2580         // 3*D
#define KP1 896           // DD padded to mult of 64
#define KP2 192           // NF padded to mult of 64

// padded-half weight scratch offsets
#define W_INPROJ 0
#define W_OUTPROJ (W_INPROJ + (size_t)QKVN*KP1)
#define W_OUTFN   (W_OUTPROJ + (size_t)DD*KP1)
#define W_FC1     (W_OUTFN + (size_t)NF*KP1)
#define W_FC2     (W_FC1 + (size_t)NF*KP1)
#define W_TOTAL   (W_FC2 + (size_t)NF*KP2)

// ---------------- scratch (__device__ globals; zero-init pads) ----------------
__device__ __half g_F[(size_t)NROWS * KP1];
__device__ __half g_QKV[(size_t)NROWS * QKVN];
__device__ __half g_CTXM[(size_t)BS * KP1];
__device__ __half g_OM[(size_t)BS * KP1];
__device__ __half g_X[(size_t)BS * KP1];
__device__ __half g_H1[(size_t)BS * KP2];
__device__ __half g_WR[W_TOTAL];

// ---------------- helpers ----------------
__device__ __forceinline__ uint32_t smem_u32(const void* p) {
    uint32_t a;
    asm("{ .reg .u64 t; cvta.to.shared.u64 t, %1; cvt.u32.u64 %0, t; }" : "=r"(a) : "l"(p));
    return a;
}
__device__ __forceinline__ void cp16(uint32_t dst, const void* src, int bytes) {
    asm volatile("cp.async.cg.shared.global [%0], [%1], 16, %2;"
                 :: "r"(dst), "l"(src), "r"(bytes));
}
__device__ __forceinline__ void cp_commit() {
    asm volatile("cp.async.commit_group;" ::: "memory");
}
template <int N>
__device__ __forceinline__ void cp_wait() {
    asm volatile("cp.async.wait_group %0;" :: "n"(N) : "memory");
}
__device__ __forceinline__ void mma_f16(float* c, const uint32_t* a, uint32_t b0, uint32_t b1) {
    asm volatile(
        "mma.sync.aligned.m16n8k16.row.col.f32.f16.f16.f32 "
        "{%0,%1,%2,%3}, {%4,%5,%6,%7}, {%8,%9}, {%0,%1,%2,%3};\n"
        : "+f"(c[0]), "+f"(c[1]), "+f"(c[2]), "+f"(c[3])
        : "r"(a[0]), "r"(a[1]), "r"(a[2]), "r"(a[3]), "r"(b0), "r"(b1));
}
__device__ __forceinline__ void ldsm_x4(uint32_t& r0, uint32_t& r1, uint32_t& r2, uint32_t& r3,
                                        uint32_t addr) {
    asm volatile("ldmatrix.sync.aligned.m8n8.x4.shared.b16 {%0,%1,%2,%3}, [%4];"
                 : "=r"(r0), "=r"(r1), "=r"(r2), "=r"(r3) : "r"(addr));
}

// ---------------- weight convert: fp32 [rows x K] -> fp16 [rows x KPad] ----------------
__global__ void cvt_w(const float* __restrict__ src, __half* __restrict__ dst,
                      int rows, int K, int KPad)
{
    int i = blockIdx.x * 256 + threadIdx.x;
    if (i < rows * K) {
        int r = i / K, c = i % K;
        dst[(size_t)r * KPad + c] = __float2half_rn(src[i]);
    }
}

// ---------------- fp16 GEMM, 128x128 tile, 3-stage, 2 CTA/SM ----------------
// C[M,N] = op(A)[M,Kp] @ B[N,Kp]^T + bias.  A,B half, K mult of 64, M mult of 128.
#define GBM 128
#define GBN 128
#define A_BYTES (GBM * 144)              // 18432 (144B padded rows)
#define B_BYTES (GBN * 144)              // 18432
#define STAGE_BYTES (A_BYTES + B_BYTES)  // 36864
#define NSTAGE 3
#define GSMEM (NSTAGE * STAGE_BYTES)     // 110592 -> 2 CTAs/SM

__device__ __forceinline__ void issue_tile(const __half* __restrict__ A,
                                           const __half* __restrict__ B,
                                           uint32_t sstage, int m0, int n0, int k0,
                                           int N, int K, int t)
{
    #pragma unroll
    for (int i = 0; i < 4; i++) {
        int id = t + (i << 8);
        int row = id >> 3;
        int c8 = (id & 7) << 3;
        const __half* src = A + (size_t)(m0 + row) * K + k0 + c8;
        cp16(sstage + row * 144 + (id & 7) * 16, src, 16);
    }
    #pragma unroll
    for (int i = 0; i < 4; i++) {
        int id = t + (i << 8);
        int row = id >> 3;
        int c8 = (id & 7) << 3;
        int bytes = (n0 + row < N) ? 16 : 0;
        const __half* src = bytes ? (B + (size_t)(n0 + row) * K + k0 + c8) : B;
        cp16(sstage + A_BYTES + row * 144 + (id & 7) * 16, src, bytes);
    }
}

__global__ void __launch_bounds__(256, 2)
gemm_f16(const __half* __restrict__ A, const __half* __restrict__ B,
         const float* __restrict__ bias,
         __half* __restrict__ C, int ldc,
         float* __restrict__ Cf, int ldcf,
         float* __restrict__ aux,
         int M, int N, int K, int relu_a)
{
    extern __shared__ __align__(16) char sm[];
    uint32_t sbase = smem_u32(sm);

    int t = threadIdx.x;
    int warp = t >> 5, lane = t & 31;
    int m0 = blockIdx.y * GBM;
    int n0 = blockIdx.x * GBN;
    int mbase = (warp & 1) * 64;       // 2 m-warps x 64
    int nbase = (warp >> 1) * 32;      // 4 n-warps x 32

    uint32_t a_lane = (uint32_t)(lane & 15) * 144 + ((lane >> 4) << 4);
    uint32_t b_lane = (uint32_t)((lane & 7) | ((lane >> 1) & 8)) * 144 + (((lane >> 3) & 1) << 4);

    float acc[4][4][4];
    #pragma unroll
    for (int mi = 0; mi < 4; mi++)
        #pragma unroll
        for (int ni = 0; ni < 4; ni++)
            #pragma unroll
            for (int r = 0; r < 4; r++) acc[mi][ni][r] = 0.0f;

    int KT = K >> 6;

    // prologue: prefetch tiles 0,1
    issue_tile(A, B, sbase, m0, n0, 0, N, K, t);
    cp_commit();
    if (KT > 1) issue_tile(A, B, sbase + STAGE_BYTES, m0, n0, 64, N, K, t);
    cp_commit();

    const __half2 hz = __float2half2_rn(0.0f);

    int scur = 0, snxt = 2;
    for (int kt = 0; kt < KT; kt++) {
        cp_wait<1>();
        __syncthreads();   // stage scur ready; all warps finished MMA on slot snxt's old data

        if (kt + 2 < KT)
            issue_tile(A, B, sbase + snxt * STAGE_BYTES, m0, n0, (kt + 2) << 6, N, K, t);
        cp_commit();

        uint32_t sA = sbase + scur * STAGE_BYTES;
        uint32_t sB = sA + A_BYTES;

        #pragma unroll
        for (int kk = 0; kk < 4; kk++) {
            uint32_t kof = (uint32_t)kk * 32;
            uint32_t a[4][4];
            #pragma unroll
            for (int mi = 0; mi < 4; mi++)
                ldsm_x4(a[mi][0], a[mi][1], a[mi][2], a[mi][3],
                        sA + (uint32_t)(mbase + mi * 16) * 144 + kof + a_lane);
            if (relu_a) {
                #pragma unroll
                for (int mi = 0; mi < 4; mi++)
                    #pragma unroll
                    for (int q = 0; q < 4; q++) {
                        __half2 h = *reinterpret_cast<__half2*>(&a[mi][q]);
                        h = __hmax2(h, hz);
                        a[mi][q] = *reinterpret_cast<uint32_t*>(&h);
                    }
            }
            uint32_t b[4][2];
            #pragma unroll
            for (int np = 0; np < 2; np++)
                ldsm_x4(b[2*np][0], b[2*np][1], b[2*np+1][0], b[2*np+1][1],
                        sB + (uint32_t)(nbase + np * 16) * 144 + kof + b_lane);
            #pragma unroll
            for (int mi = 0; mi < 4; mi++)
                #pragma unroll
                for (int ni = 0; ni < 4; ni++)
                    mma_f16(acc[mi][ni], a[mi], b[ni][0], b[ni][1]);
        }

        scur = (scur == NSTAGE - 1) ? 0 : scur + 1;
        snxt = (snxt == NSTAGE - 1) ? 0 : snxt + 1;
    }

    // epilogue
    #pragma unroll
    for (int mi = 0; mi < 4; mi++) {
        int r0 = m0 + mbase + mi * 16 + (lane >> 2);
        int r1 = r0 + 8;
        #pragma unroll
        for (int ni = 0; ni < 4; ni++) {
            int col = n0 + nbase + ni * 8 + (lane & 3) * 2;
            if (col < N) {
                float b0 = bias[col], b1 = bias[col + 1];
                float v00 = acc[mi][ni][0] + b0, v01 = acc[mi][ni][1] + b1;
                float v10 = acc[mi][ni][2] + b0, v11 = acc[mi][ni][3] + b1;
                if (C) {
                    *(__half2*)(C + (size_t)r0 * ldc + col) = __floats2half2_rn(v00, v01);
                    *(__half2*)(C + (size_t)r1 * ldc + col) = __floats2half2_rn(v10, v11);
                }
                if (Cf) {
                    Cf[(size_t)r0 * ldcf + col]     = v00;
                    Cf[(size_t)r0 * ldcf + col + 1] = v01;
                    Cf[(size_t)r1 * ldcf + col]     = v10;
                    Cf[(size_t)r1 * ldcf + col + 1] = v11;
                }
                if (aux) {
                    aux[(size_t)r0 * N + col]     = v00;
                    aux[(size_t)r0 * N + col + 1] = v01;
                    aux[(size_t)r1 * N + col]     = v10;
                    aux[(size_t)r1 * N + col + 1] = v11;
                }
            }
        }
    }
}

// ---------------- build kernel ----------------
__global__ void build_kernel(const int* __restrict__ nids,
                             const int* __restrict__ hist_nids,
                             const int* __restrict__ aids,
                             const int* __restrict__ eids,
                             const float* __restrict__ ts,
                             const int* __restrict__ dirs,
                             const float* __restrict__ node_emb,
                             const float* __restrict__ edge_emb,
                             const float* __restrict__ anony_emb,
                             const float* __restrict__ time_w,
                             const float* __restrict__ time_b,
                             float* __restrict__ out_pts)
{
    int row = blockIdx.x;
    int b = row / LH, l = row % LH;
    int hn  = hist_nids[row];
    int d   = dirs[row];
    int rn  = nids[b];
    int src = d ? rn : hn;
    int dst = d ? hn : rn;
    int aid = aids[row];
    int eid = eids[row];
    float tlast = ts[b*LH + (LH-1)];
    float dt = tlast - ts[row];
    bool last = (l == LH-1);
    __half* Frow = g_F + (size_t)row * KP1;

    for (int c = threadIdx.x; c < DD; c += blockDim.x) {
        float v;
        if      (c < 172) v = node_emb[(size_t)src*NF + c];
        else if (c < 344) v = node_emb[(size_t)dst*NF + (c-172)];
        else if (c < 516) v = anony_emb[(size_t)aid*NF + (c-344)];
        else if (c < 688) v = edge_emb[(size_t)eid*NF + (c-516)];
        else {
            int f = c - 688;
            v = cosf(dt * time_w[f] + time_b[f]);
        }
        __half hv = __float2half_rn(v);
        if (last && c < 688) {
            g_X[(size_t)b*KP1 + NF + c] = hv;
            hv = __float2half_rn(0.0f);
        }
        Frow[c] = hv;
    }
    if (last && threadIdx.x == 0) out_pts[b] = tlast;
}

// ---------------- attention + q-mean fused kernel ----------------
#define ATTN_SMEM (2 * LH * 432 * 4)

__global__ void __launch_bounds__(256)
attn_kernel(const int* __restrict__ hist_nids)
{
    extern __shared__ __align__(16) float qk[];
    float* Qs = qk;
    float* Ks = qk + LH * 432;
    __shared__ float sc[LH][LH];
    __shared__ float abar[LH];
    __shared__ int   msk[LH];

    int b = blockIdx.x;
    int t = threadIdx.x;
    int warp = t >> 5, lane = t & 31;
    const __half* qkvb = g_QKV + (size_t)b * LH * QKVN;
    const float scale = 0.048224282f;

    if (t < LH) msk[t] = (hist_nids[b*LH + t] == 0 && t != LH-1) ? 1 : 0;

    for (int h = 0; h < 2; h++) {
        int off = h * DH;
        __syncthreads();
        for (int i = t; i < LH * 432; i += 256) {
            int j = i / 432, c = i % 432;
            Qs[i] = (c < DH) ? __half2float(qkvb[(size_t)j*QKVN + off + c]) : 0.0f;
            Ks[i] = (c < DH) ? __half2float(qkvb[(size_t)j*QKVN + DD + off + c]) : 0.0f;
        }
        __syncthreads();

        int nr = (warp < 4) ? 3 : 2;
        float acc[3][LH];
        #pragma unroll
        for (int ri = 0; ri < 3; ri++)
            #pragma unroll
            for (int j = 0; j < LH; j++) acc[ri][j] = 0.0f;

        #pragma unroll
        for (int it = 0; it < 4; it++) {
            int dd = it * 128 + lane * 4;
            if (dd < 432) {
                float4 q0 = *(const float4*)(Qs + warp * 432 + dd);
                float4 q1 = *(const float4*)(Qs + (warp + 8) * 432 + dd);
                float4 q2 = (nr == 3) ? *(const float4*)(Qs + (warp + 16) * 432 + dd)
                                      : make_float4(0.f, 0.f, 0.f, 0.f);
                #pragma unroll
                for (int j = 0; j < LH; j++) {
                    float4 k4 = *(const float4*)(Ks + j * 432 + dd);
                    acc[0][j] += q0.x*k4.x + q0.y*k4.y + q0.z*k4.z + q0.w*k4.w;
                    acc[1][j] += q1.x*k4.x + q1.y*k4.y + q1.z*k4.z + q1.w*k4.w;
                    if (nr == 3)
                        acc[2][j] += q2.x*k4.x + q2.y*k4.y + q2.z*k4.z + q2.w*k4.w;
                }
            }
        }
        #pragma unroll
        for (int ri = 0; ri < 3; ri++) {
            if (ri < nr) {
                int row = warp + ri * 8;
                #pragma unroll
                for (int j = 0; j < LH; j++) {
                    float s = acc[ri][j];
                    #pragma unroll
                    for (int o = 16; o > 0; o >>= 1)
                        s += __shfl_xor_sync(0xffffffffu, s, o);
                    if (lane == 0) sc[row][j] = s * scale;
                }
            }
        }
        __syncthreads();

        if (warp == 0 && lane < LH) {
            int i = lane;
            float mx = -1e30f;
            #pragma unroll
            for (int j = 0; j < LH; j++)
                if (!msk[j]) mx = fmaxf(mx, sc[i][j]);
            float e[LH]; float s = 0.f;
            #pragma unroll
            for (int j = 0; j < LH; j++) {
                float ev = msk[j] ? 0.f : __expf(sc[i][j] - mx);
                e[j] = ev; s += ev;
            }
            float inv = 1.f / s;
            #pragma unroll
            for (int j = 0; j < LH; j++) sc[i][j] = e[j] * inv;
        }
        __syncthreads();

        if (warp == 0 && lane < LH) {
            int j = lane; float s = 0.f;
            #pragma unroll
            for (int i = 0; i < LH; i++) s += sc[i][j];
            abar[j] = s * (1.0f / LH);
        }
        __syncthreads();

        for (int dd = t; dd < DH; dd += 256) {
            float s = 0.f;
            #pragma unroll
            for (int j = 0; j < LH; j++)
                s += abar[j] * __half2float(qkvb[(size_t)j*QKVN + 2*DD + off + dd]);
            g_CTXM[(size_t)b*KP1 + off + dd] = __float2half_rn(s);
        }
    }
}

// ---------------- launch ----------------
extern "C" void kernel_launch(void* const* d_in, const int* in_sizes, int n_in,
                              void* d_out, int out_size)
{
    const int*   nids       = (const int*)  d_in[0];
    const int*   hist_nids  = (const int*)  d_in[1];
    const int*   aids       = (const int*)  d_in[2];
    const int*   eids       = (const int*)  d_in[3];
    const float* hist_ts    = (const float*)d_in[4];
    const int*   dirs       = (const int*)  d_in[5];
    const float* node_emb   = (const float*)d_in[6];
    const float* edge_emb   = (const float*)d_in[7];
    const float* anony_emb  = (const float*)d_in[8];
    const float* time_w     = (const float*)d_in[9];
    const float* time_b     = (const float*)d_in[10];
    const float* in_proj_w  = (const float*)d_in[11];
    const float* in_proj_b  = (const float*)d_in[12];
    const float* out_proj_w = (const float*)d_in[13];
    const float* out_proj_b = (const float*)d_in[14];
    const float* outfn_w    = (const float*)d_in[15];
    const float* outfn_b    = (const float*)d_in[16];
    const float* fc1_w      = (const float*)d_in[17];
    const float* fc1_b      = (const float*)d_in[18];
    const float* fc2_w      = (const float*)d_in[19];
    const float* fc2_b      = (const float*)d_in[20];

    float* out = (float*)d_out;
    float* out_hr  = out + (size_t)BS * NF;
    float* out_pts = out + (size_t)2 * BS * NF;

    __half* F    = nullptr; cudaGetSymbolAddress((void**)&F,    g_F);
    __half* QKV  = nullptr; cudaGetSymbolAddress((void**)&QKV,  g_QKV);
    __half* CTXM = nullptr; cudaGetSymbolAddress((void**)&CTXM, g_CTXM);
    __half* OM   = nullptr; cudaGetSymbolAddress((void**)&OM,   g_OM);
    __half* X    = nullptr; cudaGetSymbolAddress((void**)&X,    g_X);
    __half* H1   = nullptr; cudaGetSymbolAddress((void**)&H1,   g_H1);
    __half* WR   = nullptr; cudaGetSymbolAddress((void**)&WR,   g_WR);

    cudaFuncSetAttribute(gemm_f16, cudaFuncAttributeMaxDynamicSharedMemorySize, GSMEM);
    cudaFuncSetAttribute(attn_kernel, cudaFuncAttributeMaxDynamicSharedMemorySize, ATTN_SMEM);

    // 0) convert weights to padded fp16
    cvt_w<<<(QKVN*DD + 255)/256, 256>>>(in_proj_w,  WR + W_INPROJ,  QKVN, DD, KP1);
    cvt_w<<<(DD*DD   + 255)/256, 256>>>(out_proj_w, WR + W_OUTPROJ, DD,   DD, KP1);
    cvt_w<<<(NF*DD   + 255)/256, 256>>>(outfn_w,    WR + W_OUTFN,   NF,   DD, KP1);
    cvt_w<<<(NF*DD   + 255)/256, 256>>>(fc1_w,      WR + W_FC1,     NF,   DD, KP1);
    cvt_w<<<(NF*NF   + 255)/256, 256>>>(fc2_w,      WR + W_FC2,     NF,   NF, KP2);

    // 1) build features
    build_kernel<<<NROWS, 256>>>(nids, hist_nids, aids, eids, hist_ts, dirs,
                                 node_emb, edge_emb, anony_emb, time_w, time_b,
                                 out_pts);

    // 2) qkv = F @ in_proj_w^T + b
    gemm_f16<<<dim3((QKVN + GBN - 1)/GBN, NROWS/GBM), 256, GSMEM>>>(
        F, WR + W_INPROJ, in_proj_b, QKV, QKVN, nullptr, 0, nullptr,
        NROWS, QKVN, KP1, 0);

    // 3) attention (+ mean over queries)
    attn_kernel<<<BS, 256, ATTN_SMEM>>>(hist_nids);

    // 4) om = ctx_mean @ out_proj_w^T + b
    gemm_f16<<<dim3((DD + GBN - 1)/GBN, BS/GBM), 256, GSMEM>>>(
        CTXM, WR + W_OUTPROJ, out_proj_b, OM, KP1, nullptr, 0, nullptr,
        BS, DD, KP1, 0);

    // 5) h_prev_left = relu(om) @ outfn_w^T + b
    gemm_f16<<<dim3((NF + GBN - 1)/GBN, BS/GBM), 256, GSMEM>>>(
        OM, WR + W_OUTFN, outfn_b, X, KP1, nullptr, 0, out,
        BS, NF, KP1, 1);

    // 6) H1 = X @ fc1_w^T + b
    gemm_f16<<<dim3((NF + GBN - 1)/GBN, BS/GBM), 256, GSMEM>>>(
        X, WR + W_FC1, fc1_b, H1, KP2, nullptr, 0, nullptr,
        BS, NF, KP1, 0);

    // 7) h_prev_right = relu(H1) @ fc2_w^T + b
    gemm_f16<<<dim3((NF + GBN - 1)/GBN, BS/GBM), 256, GSMEM>>>(
        H1, WR + W_FC2, fc2_b, nullptr, 0, out_hr, NF, nullptr,
        BS, NF, KP2, 1);
}